// round 1
// baseline (speedup 1.0000x reference)
#include <cuda_runtime.h>
#include <math.h>

#define NPTS 16384
#define KNN  16
#define SPLITS 4
#define CAND_PER_SPLIT (NPTS / SPLITS)   // 4096
#define TILE_C 1024

// ---------------- scratch (device globals; no allocation allowed) ----------------
__device__ float4 g_pts[NPTS];
__device__ float  g_pd  [SPLITS * NPTS * KNN];
__device__ int    g_pidx[SPLITS * NPTS * KNN];
__device__ int    g_nbr [NPTS * KNN];
__device__ float  g_q [NPTS * 128];
__device__ float  g_k [NPTS * 128];
__device__ float  g_v [NPTS * 128];
__device__ float  g_s [NPTS * 128];
__device__ float  g_h1[NPTS * 128];
__device__ float  g_h2[NPTS * 128];

// ---------------- 0) pack coords + |p|^2 ----------------
__global__ void prep_kernel(const float* __restrict__ x) {
    int i = blockIdx.x * blockDim.x + threadIdx.x;
    if (i >= NPTS) return;
    float a = x[i * 64 + 0], b = x[i * 64 + 1], c = x[i * 64 + 2];
    g_pts[i] = make_float4(a, b, c, a * a + b * b + c * c);
}

// ---------------- 1) brute-force kNN, split into 4 candidate ranges ----------------
// block = 128 threads, each thread owns one node; block scans one split range,
// candidates staged in smem and broadcast to all lanes.
__global__ void knn_partial_kernel() {
    __shared__ float4 tile[TILE_C];
    int b = blockIdx.x;                  // 512 blocks
    int split = b >> 7;                  // 0..3
    int node = ((b & 127) << 7) + threadIdx.x;   // 128 nodes / block

    float4 p = g_pts[node];
    float nx = -2.f * p.x, ny = -2.f * p.y, nz = -2.f * p.z;

    float dist[KNN];
    int   idx [KNN];
#pragma unroll
    for (int u = 0; u < KNN; u++) { dist[u] = __int_as_float(0x7f800000); idx[u] = -1; }

    int cbase = split * CAND_PER_SPLIT;
    for (int t0 = 0; t0 < CAND_PER_SPLIT; t0 += TILE_C) {
        for (int c = threadIdx.x; c < TILE_C; c += 128)
            tile[c] = g_pts[cbase + t0 + c];
        __syncthreads();

#pragma unroll 4
        for (int c = 0; c < TILE_C; c++) {
            float4 q4 = tile[c];
            int j = cbase + t0 + c;
            // ranking distance (row-constant sq_i omitted):
            float d = fmaf(nx, q4.x, fmaf(ny, q4.y, fmaf(nz, q4.z, q4.w)));
            if (d < dist[KNN - 1] && j != node) {
                // insert into ascending sorted register list (stable: ties keep lower index)
#pragma unroll
                for (int s = KNN - 1; s >= 0; --s) {
                    float cur = dist[s];
                    if (d < cur) {
                        bool ins = (s == 0) || (d >= dist[s - 1]);
                        dist[s] = ins ? d : dist[s - 1];
                        idx [s] = ins ? j : idx [s - 1];
                    }
                }
            }
        }
        __syncthreads();
    }

    int base = (split * NPTS + node) * KNN;
#pragma unroll
    for (int u = 0; u < KNN; u++) { g_pd[base + u] = dist[u]; g_pidx[base + u] = idx[u]; }
}

// ---------------- 2) merge 4 sorted partial lists -> final 16 neighbors ----------------
__global__ void knn_merge_kernel() {
    int node = blockIdx.x * blockDim.x + threadIdx.x;
    if (node >= NPTS) return;
    int p0 = 0, p1 = 0, p2 = 0, p3 = 0;
    int b0 = (0 * NPTS + node) * KNN;
    int b1 = (1 * NPTS + node) * KNN;
    int b2 = (2 * NPTS + node) * KNN;
    int b3 = (3 * NPTS + node) * KNN;
    for (int u = 0; u < KNN; u++) {
        float d0 = g_pd[b0 + p0]; int i0 = g_pidx[b0 + p0];
        float d1 = g_pd[b1 + p1]; int i1 = g_pidx[b1 + p1];
        float d2 = g_pd[b2 + p2]; int i2 = g_pidx[b2 + p2];
        float d3 = g_pd[b3 + p3]; int i3 = g_pidx[b3 + p3];
        // lexicographic min over (d, idx)
        float bd = d0; int bi = i0; int bs = 0;
        if (d1 < bd || (d1 == bd && i1 < bi)) { bd = d1; bi = i1; bs = 1; }
        if (d2 < bd || (d2 == bd && i2 < bi)) { bd = d2; bi = i2; bs = 2; }
        if (d3 < bd || (d3 == bd && i3 < bi)) { bd = d3; bi = i3; bs = 3; }
        if      (bs == 0) p0++;
        else if (bs == 1) p1++;
        else if (bs == 2) p2++;
        else              p3++;
        g_nbr[node * KNN + u] = bi;
    }
}

// ---------------- 3) SGEMM: C[N,P] = X[N,D] @ W[D,P] + bias ----------------
#define BM 64
#define BN 64
#define BKT 16
__global__ void gemm_kernel(const float* __restrict__ X, const float* __restrict__ W,
                            const float* __restrict__ bias, float* __restrict__ C,
                            int D, int P) {
    __shared__ float As[BKT][BM];
    __shared__ float Bs[BKT][BN];
    int bm = blockIdx.x * BM;
    int bn = blockIdx.y * BN;
    int tid = threadIdx.x;              // 256 threads
    int tr = tid >> 4, tc = tid & 15;   // 16 x 16
    float acc[4][4] = {};

    for (int k0 = 0; k0 < D; k0 += BKT) {
        for (int t = tid; t < BM * BKT; t += 256) {
            int m = t >> 4, k = t & 15;
            As[k][m] = X[(size_t)(bm + m) * D + k0 + k];
        }
        for (int t = tid; t < BKT * BN; t += 256) {
            int k = t >> 6, n = t & 63;
            int nn = bn + n;
            Bs[k][n] = (nn < P) ? W[(size_t)(k0 + k) * P + nn] : 0.f;
        }
        __syncthreads();
#pragma unroll
        for (int kk = 0; kk < BKT; kk++) {
            float4 av = *(const float4*)&As[kk][tr * 4];
            float4 bv = *(const float4*)&Bs[kk][tc * 4];
            float a[4] = {av.x, av.y, av.z, av.w};
            float bb[4] = {bv.x, bv.y, bv.z, bv.w};
#pragma unroll
            for (int i = 0; i < 4; i++)
#pragma unroll
                for (int j = 0; j < 4; j++)
                    acc[i][j] = fmaf(a[i], bb[j], acc[i][j]);
        }
        __syncthreads();
    }
#pragma unroll
    for (int i = 0; i < 4; i++) {
        int row = bm + tr * 4 + i;
#pragma unroll
        for (int j = 0; j < 4; j++) {
            int col = bn + tc * 4 + j;
            if (col < P) C[(size_t)row * P + col] = acc[i][j] + bias[col];
        }
    }
}

// ---------------- 4) attention for c=128 layers (block per node) ----------------
__global__ void attn128_kernel(const float* __restrict__ qp, const float* __restrict__ kp,
                               const float* __restrict__ vp, const float* __restrict__ sp,
                               const float* __restrict__ resid, float* __restrict__ outp,
                               int do_tanh) {
    __shared__ float sq[128];
    __shared__ float al[16];
    __shared__ int   nb[16];
    int i = blockIdx.x;
    int t = threadIdx.x;
    if (t < 16) nb[t] = g_nbr[i * 16 + t];
    sq[t] = qp[(size_t)i * 128 + t];
    __syncthreads();

    int w = t >> 5, l = t & 31;
#pragma unroll
    for (int ee = 0; ee < 4; ee++) {
        int e = (w << 2) + ee;
        int j = nb[e];
        const float* kj = kp + (size_t)j * 128;
        float a = sq[l] * kj[l];
        a = fmaf(sq[l + 32], kj[l + 32], a);
        a = fmaf(sq[l + 64], kj[l + 64], a);
        a = fmaf(sq[l + 96], kj[l + 96], a);
#pragma unroll
        for (int o = 16; o > 0; o >>= 1) a += __shfl_xor_sync(0xffffffffu, a, o);
        if (l == 0) al[e] = a * 0.08838834764831845f;   // 1/sqrt(128)
    }
    __syncthreads();
    if (t < 32) {
        float a = (l < 16) ? al[l] : -__int_as_float(0x7f800000);
        float m = a;
#pragma unroll
        for (int o = 16; o > 0; o >>= 1) m = fmaxf(m, __shfl_xor_sync(0xffffffffu, m, o));
        float ex = (l < 16) ? expf(a - m) : 0.f;
        float sm = ex;
#pragma unroll
        for (int o = 16; o > 0; o >>= 1) sm += __shfl_xor_sync(0xffffffffu, sm, o);
        if (l < 16) al[l] = ex / sm;
    }
    __syncthreads();

    float acc = sp[(size_t)i * 128 + t];
#pragma unroll
    for (int e = 0; e < 16; e++)
        acc = fmaf(al[e], vp[(size_t)nb[e] * 128 + t], acc);
    if (resid) acc += resid[(size_t)i * 128 + t];
    outp[(size_t)i * 128 + t] = do_tanh ? tanhf(acc) : acc;
}

// ---------------- 5) attention for c=3 final layer (warp per node) ----------------
__global__ void attn3_kernel(float* __restrict__ outp) {
    int gt = blockIdx.x * blockDim.x + threadIdx.x;
    int i = gt >> 5;
    int l = gt & 31;
    if (i >= NPTS) return;
    int j = 0;
    float a = -__int_as_float(0x7f800000);
    if (l < 16) {
        j = g_nbr[i * 16 + l];
        float qx = g_q[i * 3], qy = g_q[i * 3 + 1], qz = g_q[i * 3 + 2];
        a = fmaf(qx, g_k[j * 3], fmaf(qy, g_k[j * 3 + 1], qz * g_k[j * 3 + 2]))
            * 0.5773502691896258f;   // 1/sqrt(3)
    }
    float m = a;
#pragma unroll
    for (int o = 16; o > 0; o >>= 1) m = fmaxf(m, __shfl_xor_sync(0xffffffffu, m, o));
    float ex = (l < 16) ? expf(a - m) : 0.f;
    float sm = ex;
#pragma unroll
    for (int o = 16; o > 0; o >>= 1) sm += __shfl_xor_sync(0xffffffffu, sm, o);
    float wgt = ex / sm;
    float vx = 0.f, vy = 0.f, vz = 0.f;
    if (l < 16) {
        vx = wgt * g_v[j * 3];
        vy = wgt * g_v[j * 3 + 1];
        vz = wgt * g_v[j * 3 + 2];
    }
#pragma unroll
    for (int o = 16; o > 0; o >>= 1) {
        vx += __shfl_xor_sync(0xffffffffu, vx, o);
        vy += __shfl_xor_sync(0xffffffffu, vy, o);
        vz += __shfl_xor_sync(0xffffffffu, vz, o);
    }
    if (l == 0) {
        outp[i * 3 + 0] = vx + g_s[i * 3 + 0];
        outp[i * 3 + 1] = vy + g_s[i * 3 + 1];
        outp[i * 3 + 2] = vz + g_s[i * 3 + 2];
    }
}

// ---------------- host ----------------
extern "C" void kernel_launch(void* const* d_in, const int* in_sizes, int n_in,
                              void* d_out, int out_size) {
    const float* x = (const float*)d_in[1];
    const float* W1[4] = {(const float*)d_in[2], (const float*)d_in[4],
                          (const float*)d_in[6], (const float*)d_in[8]};
    const float* B1[4] = {(const float*)d_in[3], (const float*)d_in[5],
                          (const float*)d_in[7], (const float*)d_in[9]};
    const float* W2[4] = {(const float*)d_in[10], (const float*)d_in[12],
                          (const float*)d_in[14], (const float*)d_in[16]};
    const float* B2[4] = {(const float*)d_in[11], (const float*)d_in[13],
                          (const float*)d_in[15], (const float*)d_in[17]};
    const float* W3[4] = {(const float*)d_in[18], (const float*)d_in[20],
                          (const float*)d_in[22], (const float*)d_in[24]};
    const float* B3[4] = {(const float*)d_in[19], (const float*)d_in[21],
                          (const float*)d_in[23], (const float*)d_in[25]};
    float* out = (float*)d_out;

    float *q, *k, *v, *s, *h1, *h2;
    cudaGetSymbolAddress((void**)&q,  g_q);
    cudaGetSymbolAddress((void**)&k,  g_k);
    cudaGetSymbolAddress((void**)&v,  g_v);
    cudaGetSymbolAddress((void**)&s,  g_s);
    cudaGetSymbolAddress((void**)&h1, g_h1);
    cudaGetSymbolAddress((void**)&h2, g_h2);
    float* proj[4] = {q, k, v, s};

    // kNN graph
    prep_kernel<<<NPTS / 256, 256>>>(x);
    knn_partial_kernel<<<SPLITS * (NPTS / 128), 128>>>();
    knn_merge_kernel<<<NPTS / 256, 256>>>();

    // layer 1: x[16384,64] -> h1
    for (int p = 0; p < 4; p++) {
        dim3 grid(NPTS / BM, (128 + BN - 1) / BN);
        gemm_kernel<<<grid, 256>>>(x, W1[p], B1[p], proj[p], 64, 128);
    }
    attn128_kernel<<<NPTS, 128>>>(q, k, v, s, nullptr, h1, 1);

    // layer 2: h1 -> h2 (with residual)
    for (int p = 0; p < 4; p++) {
        dim3 grid(NPTS / BM, (128 + BN - 1) / BN);
        gemm_kernel<<<grid, 256>>>(h1, W2[p], B2[p], proj[p], 128, 128);
    }
    attn128_kernel<<<NPTS, 128>>>(q, k, v, s, h1, h2, 1);

    // layer 3: h2 -> out[16384,3]
    for (int p = 0; p < 4; p++) {
        dim3 grid(NPTS / BM, 1);
        gemm_kernel<<<grid, 256>>>(h2, W3[p], B3[p], proj[p], 128, 3);
    }
    attn3_kernel<<<(NPTS * 32) / 128, 128>>>(out);
}

// round 2
// speedup vs baseline: 1.2359x; 1.2359x over previous
#include <cuda_runtime.h>
#include <math.h>

#define NPTS 16384
#define KNN  16
#define SPLITS 4
#define CAND_PER_SPLIT (NPTS / SPLITS)   // 4096
#define TILE_C 1024
#define BUFCAP 8

// ---------------- scratch (device globals; no allocation allowed) ----------------
__device__ float4 g_pts[NPTS];
__device__ float  g_pd  [SPLITS * NPTS * KNN];
__device__ int    g_pidx[SPLITS * NPTS * KNN];
__device__ int    g_nbr [NPTS * KNN];
__device__ float  g_qkvs[NPTS * 512];     // packed Q|K|V|S projections
__device__ float  g_h1 [NPTS * 128];
__device__ float  g_h2 [NPTS * 128];
__device__ float  g_Wp1[64  * 512];
__device__ float  g_Wp2[128 * 512];
__device__ float  g_Wp3[128 * 12];
__device__ float  g_Bp1[512];
__device__ float  g_Bp2[512];
__device__ float  g_Bp3[12];

// ---------------- weight / bias packing ----------------
__global__ void pack_w_kernel(const float* __restrict__ a, const float* __restrict__ b,
                              const float* __restrict__ c, const float* __restrict__ d,
                              float* __restrict__ dst, int D, int Pp) {
    int i = blockIdx.x * blockDim.x + threadIdx.x;
    if (i >= D * Pp) return;
    int r = i / Pp, col = i - r * Pp;
    float* o = dst + (size_t)r * 4 * Pp + col;
    o[0 * Pp] = a[i]; o[1 * Pp] = b[i]; o[2 * Pp] = c[i]; o[3 * Pp] = d[i];
}

__global__ void pack_b_kernel(const float* __restrict__ a, const float* __restrict__ b,
                              const float* __restrict__ c, const float* __restrict__ d,
                              float* __restrict__ dst, int Pp) {
    int i = blockIdx.x * blockDim.x + threadIdx.x;
    if (i >= Pp) return;
    dst[i] = a[i]; dst[Pp + i] = b[i]; dst[2 * Pp + i] = c[i]; dst[3 * Pp + i] = d[i];
}

// ---------------- pack coords + |p|^2 ----------------
__global__ void prep_kernel(const float* __restrict__ x) {
    int i = blockIdx.x * blockDim.x + threadIdx.x;
    if (i >= NPTS) return;
    float a = x[i * 64 + 0], b = x[i * 64 + 1], c = x[i * 64 + 2];
    g_pts[i] = make_float4(a, b, c, a * a + b * b + c * c);
}

// stable ascending insert of (d, j) into 16-deep register list
__device__ __forceinline__ void insert16(float (&dist)[KNN], int (&idx)[KNN],
                                         float d, int j) {
#pragma unroll
    for (int s = KNN - 1; s >= 0; --s) {
        float cur = dist[s];
        if (d < cur) {
            bool ins = (s == 0) || (d >= dist[s - 1]);
            dist[s] = ins ? d : dist[s - 1];
            idx [s] = ins ? j : idx [s - 1];
        }
    }
}

// ---------------- brute-force kNN with buffered insertion ----------------
// block = 128 threads; each thread owns one node; block scans one split range.
// Candidates below the (stale) threshold go to a small smem buffer; the costly
// insertion chain runs only on warp-collective flushes.
__global__ void knn_partial_kernel() {
    __shared__ float4 tile[TILE_C];
    __shared__ float  sbd[BUFCAP * 128];
    __shared__ int    sbi[BUFCAP * 128];
    int b = blockIdx.x;                  // 512 blocks
    int split = b >> 7;
    int t = threadIdx.x;
    int node = ((b & 127) << 7) + t;

    float4 p = g_pts[node];
    float nx = -2.f * p.x, ny = -2.f * p.y, nz = -2.f * p.z;

    float dist[KNN];
    int   idx [KNN];
#pragma unroll
    for (int u = 0; u < KNN; u++) { dist[u] = __int_as_float(0x7f800000); idx[u] = -1; }
    float thresh = __int_as_float(0x7f800000);
    int cnt = 0;

    int cbase = split * CAND_PER_SPLIT;
    for (int t0 = 0; t0 < CAND_PER_SPLIT; t0 += TILE_C) {
        for (int c = t; c < TILE_C; c += 128)
            tile[c] = g_pts[cbase + t0 + c];
        __syncthreads();

#pragma unroll 4
        for (int c = 0; c < TILE_C; c++) {
            float4 q4 = tile[c];
            float d = fmaf(nx, q4.x, fmaf(ny, q4.y, fmaf(nz, q4.z, q4.w)));
            bool pass = d < thresh;
            if (__ballot_sync(0xffffffffu, pass)) {
                if (pass) {
                    sbd[cnt * 128 + t] = d;
                    sbi[cnt * 128 + t] = cbase + t0 + c;
                    cnt++;
                }
                if (__any_sync(0xffffffffu, cnt == BUFCAP)) {
                    for (int u = 0; u < cnt; u++) {
                        float dd = sbd[u * 128 + t];
                        int   jj = sbi[u * 128 + t];
                        if (jj != node) insert16(dist, idx, dd, jj);
                    }
                    cnt = 0;
                    thresh = dist[KNN - 1];
                }
            }
        }
        __syncthreads();
    }
    for (int u = 0; u < cnt; u++) {
        float dd = sbd[u * 128 + t];
        int   jj = sbi[u * 128 + t];
        if (jj != node) insert16(dist, idx, dd, jj);
    }

    int base = (split * NPTS + node) * KNN;
#pragma unroll
    for (int u = 0; u < KNN; u++) { g_pd[base + u] = dist[u]; g_pidx[base + u] = idx[u]; }
}

// ---------------- merge 4 sorted partial lists -> final 16 neighbors ----------------
__global__ void knn_merge_kernel() {
    int node = blockIdx.x * blockDim.x + threadIdx.x;
    if (node >= NPTS) return;
    int p0 = 0, p1 = 0, p2 = 0, p3 = 0;
    int b0 = (0 * NPTS + node) * KNN;
    int b1 = (1 * NPTS + node) * KNN;
    int b2 = (2 * NPTS + node) * KNN;
    int b3 = (3 * NPTS + node) * KNN;
    for (int u = 0; u < KNN; u++) {
        float d0 = g_pd[b0 + p0]; int i0 = g_pidx[b0 + p0];
        float d1 = g_pd[b1 + p1]; int i1 = g_pidx[b1 + p1];
        float d2 = g_pd[b2 + p2]; int i2 = g_pidx[b2 + p2];
        float d3 = g_pd[b3 + p3]; int i3 = g_pidx[b3 + p3];
        float bd = d0; int bi = i0; int bs = 0;
        if (d1 < bd || (d1 == bd && i1 < bi)) { bd = d1; bi = i1; bs = 1; }
        if (d2 < bd || (d2 == bd && i2 < bi)) { bd = d2; bi = i2; bs = 2; }
        if (d3 < bd || (d3 == bd && i3 < bi)) { bd = d3; bi = i3; bs = 3; }
        if      (bs == 0) p0++;
        else if (bs == 1) p1++;
        else if (bs == 2) p2++;
        else              p3++;
        g_nbr[node * KNN + u] = bi;
    }
}

// ---------------- big SGEMM: C[N,P] = X[N,D] @ W[D,P] + bias ----------------
// 128x128 block tile, 16 k-slice, 256 threads, 8x8 register tile.
#define GBM 128
#define GBN 128
#define GBK 16
__global__ void __launch_bounds__(256)
gemm128_kernel(const float* __restrict__ X, const float* __restrict__ W,
               const float* __restrict__ bias, float* __restrict__ C,
               int D, int P) {
    __shared__ float As[GBK][GBM];
    __shared__ float Bs[GBK][GBN];
    int tid = threadIdx.x;
    int bm = blockIdx.x * GBM;
    int bn = blockIdx.y * GBN;

    int ar = tid >> 1;              // A: 2 threads per row, 8 k each
    int ak = (tid & 1) << 3;
    int bk = tid >> 5;              // B: 8 rows x 32 thr, float4 cols
    int bc = (tid & 31) << 2;
    int tr = tid >> 4, tc = tid & 15;

    const float* xr = X + (size_t)(bm + ar) * D + ak;
    float acc[8][8] = {};

    for (int k0 = 0; k0 < D; k0 += GBK) {
        float4 a0 = *(const float4*)(xr + k0);
        float4 a1 = *(const float4*)(xr + k0 + 4);
        As[ak + 0][ar] = a0.x; As[ak + 1][ar] = a0.y;
        As[ak + 2][ar] = a0.z; As[ak + 3][ar] = a0.w;
        As[ak + 4][ar] = a1.x; As[ak + 5][ar] = a1.y;
        As[ak + 6][ar] = a1.z; As[ak + 7][ar] = a1.w;
        *(float4*)&Bs[bk][bc] =
            *(const float4*)(W + (size_t)(k0 + bk) * P + bn + bc);
        *(float4*)&Bs[bk + 8][bc] =
            *(const float4*)(W + (size_t)(k0 + bk + 8) * P + bn + bc);
        __syncthreads();
#pragma unroll
        for (int kk = 0; kk < GBK; kk++) {
            float4 av0 = *(const float4*)&As[kk][tr * 8];
            float4 av1 = *(const float4*)&As[kk][tr * 8 + 4];
            float4 bv0 = *(const float4*)&Bs[kk][tc * 8];
            float4 bv1 = *(const float4*)&Bs[kk][tc * 8 + 4];
            float a[8] = {av0.x, av0.y, av0.z, av0.w, av1.x, av1.y, av1.z, av1.w};
            float bb[8] = {bv0.x, bv0.y, bv0.z, bv0.w, bv1.x, bv1.y, bv1.z, bv1.w};
#pragma unroll
            for (int i = 0; i < 8; i++)
#pragma unroll
                for (int j = 0; j < 8; j++)
                    acc[i][j] = fmaf(a[i], bb[j], acc[i][j]);
        }
        __syncthreads();
    }

    float bb0[8];
#pragma unroll
    for (int j = 0; j < 8; j++) bb0[j] = bias[bn + tc * 8 + j];
#pragma unroll
    for (int i = 0; i < 8; i++) {
        size_t row = bm + tr * 8 + i;
        float4 o0 = make_float4(acc[i][0] + bb0[0], acc[i][1] + bb0[1],
                                acc[i][2] + bb0[2], acc[i][3] + bb0[3]);
        float4 o1 = make_float4(acc[i][4] + bb0[4], acc[i][5] + bb0[5],
                                acc[i][6] + bb0[6], acc[i][7] + bb0[7]);
        *(float4*)(C + row * P + bn + tc * 8)     = o0;
        *(float4*)(C + row * P + bn + tc * 8 + 4) = o1;
    }
}

// ---------------- small SGEMM (layer 3, P=12), bounds-checked ----------------
#define BM 64
#define BN 64
#define BKT 16
__global__ void gemm_kernel(const float* __restrict__ X, const float* __restrict__ W,
                            const float* __restrict__ bias, float* __restrict__ C,
                            int D, int P) {
    __shared__ float As[BKT][BM];
    __shared__ float Bs[BKT][BN];
    int bm = blockIdx.x * BM;
    int bn = blockIdx.y * BN;
    int tid = threadIdx.x;
    int tr = tid >> 4, tc = tid & 15;
    float acc[4][4] = {};

    for (int k0 = 0; k0 < D; k0 += BKT) {
        for (int t = tid; t < BM * BKT; t += 256) {
            int m = t >> 4, k = t & 15;
            As[k][m] = X[(size_t)(bm + m) * D + k0 + k];
        }
        for (int t = tid; t < BKT * BN; t += 256) {
            int k = t >> 6, n = t & 63;
            int nn = bn + n;
            Bs[k][n] = (nn < P) ? W[(size_t)(k0 + k) * P + nn] : 0.f;
        }
        __syncthreads();
#pragma unroll
        for (int kk = 0; kk < BKT; kk++) {
            float4 av = *(const float4*)&As[kk][tr * 4];
            float4 bv = *(const float4*)&Bs[kk][tc * 4];
            float a[4] = {av.x, av.y, av.z, av.w};
            float bb[4] = {bv.x, bv.y, bv.z, bv.w};
#pragma unroll
            for (int i = 0; i < 4; i++)
#pragma unroll
                for (int j = 0; j < 4; j++)
                    acc[i][j] = fmaf(a[i], bb[j], acc[i][j]);
        }
        __syncthreads();
    }
#pragma unroll
    for (int i = 0; i < 4; i++) {
        int row = bm + tr * 4 + i;
#pragma unroll
        for (int j = 0; j < 4; j++) {
            int col = bn + tc * 4 + j;
            if (col < P) C[(size_t)row * P + col] = acc[i][j] + bias[col];
        }
    }
}

// ---------------- attention, c=128 layers (block per node); packed QKVS ----------------
__global__ void attn128_kernel(const float* __restrict__ pk,
                               const float* __restrict__ resid,
                               float* __restrict__ outp, int do_tanh) {
    __shared__ float sq[128];
    __shared__ float al[16];
    __shared__ int   nb[16];
    int i = blockIdx.x;
    int t = threadIdx.x;
    if (t < 16) nb[t] = g_nbr[i * 16 + t];
    sq[t] = pk[(size_t)i * 512 + t];            // Q at offset 0
    __syncthreads();

    int w = t >> 5, l = t & 31;
#pragma unroll
    for (int ee = 0; ee < 4; ee++) {
        int e = (w << 2) + ee;
        int j = nb[e];
        const float* kj = pk + (size_t)j * 512 + 128;   // K at offset 128
        float a = sq[l] * kj[l];
        a = fmaf(sq[l + 32], kj[l + 32], a);
        a = fmaf(sq[l + 64], kj[l + 64], a);
        a = fmaf(sq[l + 96], kj[l + 96], a);
#pragma unroll
        for (int o = 16; o > 0; o >>= 1) a += __shfl_xor_sync(0xffffffffu, a, o);
        if (l == 0) al[e] = a * 0.08838834764831845f;   // 1/sqrt(128)
    }
    __syncthreads();
    if (t < 32) {
        float a = (l < 16) ? al[l] : -__int_as_float(0x7f800000);
        float m = a;
#pragma unroll
        for (int o = 16; o > 0; o >>= 1) m = fmaxf(m, __shfl_xor_sync(0xffffffffu, m, o));
        float ex = (l < 16) ? expf(a - m) : 0.f;
        float sm = ex;
#pragma unroll
        for (int o = 16; o > 0; o >>= 1) sm += __shfl_xor_sync(0xffffffffu, sm, o);
        if (l < 16) al[l] = ex / sm;
    }
    __syncthreads();

    float acc = pk[(size_t)i * 512 + 384 + t];          // S at offset 384
#pragma unroll
    for (int e = 0; e < 16; e++)
        acc = fmaf(al[e], pk[(size_t)nb[e] * 512 + 256 + t], acc);  // V at 256
    if (resid) acc += resid[(size_t)i * 128 + t];
    outp[(size_t)i * 128 + t] = do_tanh ? tanhf(acc) : acc;
}

// ---------------- attention, c=3 final layer (warp per node); packed P=12 ----------------
__global__ void attn3_kernel(const float* __restrict__ pk, float* __restrict__ outp) {
    int gt = blockIdx.x * blockDim.x + threadIdx.x;
    int i = gt >> 5;
    int l = gt & 31;
    if (i >= NPTS) return;
    int j = 0;
    float a = -__int_as_float(0x7f800000);
    if (l < 16) {
        j = g_nbr[i * 16 + l];
        float qx = pk[i * 12 + 0], qy = pk[i * 12 + 1], qz = pk[i * 12 + 2];
        a = fmaf(qx, pk[j * 12 + 3], fmaf(qy, pk[j * 12 + 4], qz * pk[j * 12 + 5]))
            * 0.5773502691896258f;   // 1/sqrt(3)
    }
    float m = a;
#pragma unroll
    for (int o = 16; o > 0; o >>= 1) m = fmaxf(m, __shfl_xor_sync(0xffffffffu, m, o));
    float ex = (l < 16) ? expf(a - m) : 0.f;
    float sm = ex;
#pragma unroll
    for (int o = 16; o > 0; o >>= 1) sm += __shfl_xor_sync(0xffffffffu, sm, o);
    float wgt = ex / sm;
    float vx = 0.f, vy = 0.f, vz = 0.f;
    if (l < 16) {
        vx = wgt * pk[j * 12 + 6];
        vy = wgt * pk[j * 12 + 7];
        vz = wgt * pk[j * 12 + 8];
    }
#pragma unroll
    for (int o = 16; o > 0; o >>= 1) {
        vx += __shfl_xor_sync(0xffffffffu, vx, o);
        vy += __shfl_xor_sync(0xffffffffu, vy, o);
        vz += __shfl_xor_sync(0xffffffffu, vz, o);
    }
    if (l == 0) {
        outp[i * 3 + 0] = vx + pk[i * 12 + 9];
        outp[i * 3 + 1] = vy + pk[i * 12 + 10];
        outp[i * 3 + 2] = vz + pk[i * 12 + 11];
    }
}

// ---------------- host ----------------
extern "C" void kernel_launch(void* const* d_in, const int* in_sizes, int n_in,
                              void* d_out, int out_size) {
    const float* x = (const float*)d_in[1];
    const float* W1[4] = {(const float*)d_in[2], (const float*)d_in[4],
                          (const float*)d_in[6], (const float*)d_in[8]};
    const float* B1[4] = {(const float*)d_in[3], (const float*)d_in[5],
                          (const float*)d_in[7], (const float*)d_in[9]};
    const float* W2[4] = {(const float*)d_in[10], (const float*)d_in[12],
                          (const float*)d_in[14], (const float*)d_in[16]};
    const float* B2[4] = {(const float*)d_in[11], (const float*)d_in[13],
                          (const float*)d_in[15], (const float*)d_in[17]};
    const float* W3[4] = {(const float*)d_in[18], (const float*)d_in[20],
                          (const float*)d_in[22], (const float*)d_in[24]};
    const float* B3[4] = {(const float*)d_in[19], (const float*)d_in[21],
                          (const float*)d_in[23], (const float*)d_in[25]};
    float* out = (float*)d_out;

    float *qkvs, *h1, *h2, *Wp1, *Wp2, *Wp3, *Bp1, *Bp2, *Bp3;
    cudaGetSymbolAddress((void**)&qkvs, g_qkvs);
    cudaGetSymbolAddress((void**)&h1,  g_h1);
    cudaGetSymbolAddress((void**)&h2,  g_h2);
    cudaGetSymbolAddress((void**)&Wp1, g_Wp1);
    cudaGetSymbolAddress((void**)&Wp2, g_Wp2);
    cudaGetSymbolAddress((void**)&Wp3, g_Wp3);
    cudaGetSymbolAddress((void**)&Bp1, g_Bp1);
    cudaGetSymbolAddress((void**)&Bp2, g_Bp2);
    cudaGetSymbolAddress((void**)&Bp3, g_Bp3);

    // (1..3) pack biases, (4) pack weights for L2/L3 via 3 launches collapsed:
    pack_b_kernel<<<1, 128>>>(B1[0], B1[1], B1[2], B1[3], Bp1, 128);
    pack_b_kernel<<<1, 128>>>(B2[0], B2[1], B2[2], B2[3], Bp2, 128);
    pack_b_kernel<<<1, 128>>>(B3[0], B3[1], B3[2], B3[3], Bp3, 3);
    pack_w_kernel<<<(64 * 128 + 255) / 256, 256>>>(W1[0], W1[1], W1[2], W1[3], Wp1, 64, 128);
    // (5) prep — then (6) knn_partial lands on ncu's captured launch (-s 5 -c 1)
    prep_kernel<<<NPTS / 256, 256>>>(x);
    knn_partial_kernel<<<SPLITS * (NPTS / 128), 128>>>();
    knn_merge_kernel<<<NPTS / 256, 256>>>();
    pack_w_kernel<<<(128 * 128 + 255) / 256, 256>>>(W2[0], W2[1], W2[2], W2[3], Wp2, 128, 128);
    pack_w_kernel<<<(128 * 3 + 255) / 256, 256>>>(W3[0], W3[1], W3[2], W3[3], Wp3, 128, 3);

    // layer 1: x[16384,64] @ Wp1[64,512] -> qkvs, attn -> h1
    {
        dim3 grid(NPTS / GBM, 512 / GBN);
        gemm128_kernel<<<grid, 256>>>(x, Wp1, Bp1, qkvs, 64, 512);
    }
    attn128_kernel<<<NPTS, 128>>>(qkvs, nullptr, h1, 1);

    // layer 2: h1 @ Wp2[128,512] -> qkvs, attn(+h1 resid) -> h2
    {
        dim3 grid(NPTS / GBM, 512 / GBN);
        gemm128_kernel<<<grid, 256>>>(h1, Wp2, Bp2, qkvs, 128, 512);
    }
    attn128_kernel<<<NPTS, 128>>>(qkvs, h1, h2, 1);

    // layer 3: h2 @ Wp3[128,12] -> qkvs (reused), attn3 -> out
    {
        dim3 grid(NPTS / BM, 1);
        gemm_kernel<<<grid, 256>>>(h2, Wp3, Bp3, qkvs, 128, 12);
    }
    attn3_kernel<<<(NPTS * 32) / 128, 128>>>(qkvs, out);
}

// round 3
// speedup vs baseline: 1.4970x; 1.2112x over previous
#include <cuda_runtime.h>
#include <math.h>

#define NPTS 16384
#define KNN  16
#define SPLITS 8
#define CAND_PER_SPLIT (NPTS / SPLITS)   // 2048
#define TILE_C 512
#define BUFCAP 40
#define CHUNK 32

// ---------------- scratch (device globals; no allocation allowed) ----------------
__device__ float4 g_pts[NPTS];
__device__ float  g_pd  [SPLITS * NPTS * KNN];
__device__ int    g_pidx[SPLITS * NPTS * KNN];
__device__ int    g_nbr [NPTS * KNN];
__device__ float  g_qkvs[NPTS * 512];     // packed Q|K|V|S projections
__device__ float  g_h1 [NPTS * 128];
__device__ float  g_h2 [NPTS * 128];
__device__ float  g_Wp1[64  * 512];
__device__ float  g_Wp2[128 * 512];
__device__ float  g_Wp3[128 * 12];
__device__ float  g_Bp1[512];
__device__ float  g_Bp2[512];
__device__ float  g_Bp3[12];

// ---------------- weight / bias packing ----------------
__global__ void pack_w_kernel(const float* __restrict__ a, const float* __restrict__ b,
                              const float* __restrict__ c, const float* __restrict__ d,
                              float* __restrict__ dst, int D, int Pp) {
    int i = blockIdx.x * blockDim.x + threadIdx.x;
    if (i >= D * Pp) return;
    int r = i / Pp, col = i - r * Pp;
    float* o = dst + (size_t)r * 4 * Pp + col;
    o[0 * Pp] = a[i]; o[1 * Pp] = b[i]; o[2 * Pp] = c[i]; o[3 * Pp] = d[i];
}

__global__ void pack_b_kernel(const float* __restrict__ a, const float* __restrict__ b,
                              const float* __restrict__ c, const float* __restrict__ d,
                              float* __restrict__ dst, int Pp) {
    int i = blockIdx.x * blockDim.x + threadIdx.x;
    if (i >= Pp) return;
    dst[i] = a[i]; dst[Pp + i] = b[i]; dst[2 * Pp + i] = c[i]; dst[3 * Pp + i] = d[i];
}

// ---------------- pack coords + |p|^2 ----------------
__global__ void prep_kernel(const float* __restrict__ x) {
    int i = blockIdx.x * blockDim.x + threadIdx.x;
    if (i >= NPTS) return;
    float a = x[i * 64 + 0], b = x[i * 64 + 1], c = x[i * 64 + 2];
    g_pts[i] = make_float4(a, b, c, a * a + b * b + c * c);
}

// stable ascending insert of (d, j) into 16-deep register list
__device__ __forceinline__ void insert16(float (&dist)[KNN], int (&idx)[KNN],
                                         float d, int j) {
#pragma unroll
    for (int s = KNN - 1; s >= 0; --s) {
        float cur = dist[s];
        if (d < cur) {
            bool ins = (s == 0) || (d >= dist[s - 1]);
            dist[s] = ins ? d : dist[s - 1];
            idx [s] = ins ? j : idx [s - 1];
        }
    }
}

// ---------------- brute-force kNN, chunked buffered insertion ----------------
// block = 128 threads; each thread owns one node; block scans one split range.
// Pure predicated per-candidate path; one warp vote per 32-candidate chunk.
__global__ void __launch_bounds__(128) knn_partial_kernel() {
    __shared__ float4 tile[TILE_C];
    __shared__ float  sbd[BUFCAP * 128];
    __shared__ unsigned short sbi[BUFCAP * 128];
    int b = blockIdx.x;                  // 1024 blocks
    int split = b >> 7;                  // 0..7
    int t = threadIdx.x;
    int node = ((b & 127) << 7) + t;

    float4 p = g_pts[node];
    float nx = -2.f * p.x, ny = -2.f * p.y, nz = -2.f * p.z;

    float dist[KNN];
    int   idx [KNN];
#pragma unroll
    for (int u = 0; u < KNN; u++) { dist[u] = __int_as_float(0x7f800000); idx[u] = -1; }
    float thresh = __int_as_float(0x7f800000);
    int cnt = 0;

    int cbase = split * CAND_PER_SPLIT;
    for (int t0 = 0; t0 < CAND_PER_SPLIT; t0 += TILE_C) {
        for (int c = t; c < TILE_C; c += 128)
            tile[c] = g_pts[cbase + t0 + c];
        __syncthreads();

        for (int c0 = 0; c0 < TILE_C; c0 += CHUNK) {
#pragma unroll
            for (int cc = 0; cc < CHUNK; cc++) {
                float4 q4 = tile[c0 + cc];
                int j = cbase + t0 + c0 + cc;
                float d = fmaf(nx, q4.x, fmaf(ny, q4.y, fmaf(nz, q4.z, q4.w)));
                if (d < thresh && j != node) {
                    sbd[cnt * 128 + t] = d;
                    sbi[cnt * 128 + t] = (unsigned short)j;
                    cnt++;
                }
            }
            if (__any_sync(0xffffffffu, cnt >= BUFCAP - CHUNK)) {
                int m = cnt;
#pragma unroll
                for (int o = 16; o > 0; o >>= 1)
                    m = max(m, __shfl_xor_sync(0xffffffffu, m, o));
                for (int u = 0; u < m; u++) {
                    if (u < cnt) {
                        float dd = sbd[u * 128 + t];
                        int   jj = sbi[u * 128 + t];
                        insert16(dist, idx, dd, jj);
                    }
                }
                cnt = 0;
                thresh = dist[KNN - 1];
            }
        }
        __syncthreads();
    }
    {
        int m = cnt;
#pragma unroll
        for (int o = 16; o > 0; o >>= 1)
            m = max(m, __shfl_xor_sync(0xffffffffu, m, o));
        for (int u = 0; u < m; u++) {
            if (u < cnt) {
                float dd = sbd[u * 128 + t];
                int   jj = sbi[u * 128 + t];
                insert16(dist, idx, dd, jj);
            }
        }
    }

    int base = (split * NPTS + node) * KNN;
#pragma unroll
    for (int u = 0; u < KNN; u++) { g_pd[base + u] = dist[u]; g_pidx[base + u] = idx[u]; }
}

// ---------------- merge 8 sorted partial lists -> final 16 neighbors ----------------
__global__ void knn_merge_kernel() {
    int node = blockIdx.x * blockDim.x + threadIdx.x;
    if (node >= NPTS) return;
    int ptr[SPLITS];
#pragma unroll
    for (int s = 0; s < SPLITS; s++) ptr[s] = 0;
    for (int u = 0; u < KNN; u++) {
        float bd = __int_as_float(0x7f800000);
        int bi = 0x7fffffff, bs = 0;
#pragma unroll
        for (int s = 0; s < SPLITS; s++) {
            int off = (s * NPTS + node) * KNN + ptr[s];
            float d = g_pd[off];
            int   i2 = g_pidx[off];
            if (d < bd || (d == bd && i2 < bi)) { bd = d; bi = i2; bs = s; }
        }
        ptr[bs]++;
        g_nbr[node * KNN + u] = bi;
    }
}

// ---------------- big SGEMM: C[N,P] = X[N,D] @ W[D,P] + bias ----------------
#define GBM 128
#define GBN 128
#define GBK 16
__global__ void __launch_bounds__(256)
gemm128_kernel(const float* __restrict__ X, const float* __restrict__ W,
               const float* __restrict__ bias, float* __restrict__ C,
               int D, int P) {
    __shared__ float As[GBK][GBM];
    __shared__ float Bs[GBK][GBN];
    int tid = threadIdx.x;
    int bm = blockIdx.x * GBM;
    int bn = blockIdx.y * GBN;

    int ar = tid >> 1;
    int ak = (tid & 1) << 3;
    int bk = tid >> 5;
    int bc = (tid & 31) << 2;
    int tr = tid >> 4, tc = tid & 15;

    const float* xr = X + (size_t)(bm + ar) * D + ak;
    float acc[8][8] = {};

    for (int k0 = 0; k0 < D; k0 += GBK) {
        float4 a0 = *(const float4*)(xr + k0);
        float4 a1 = *(const float4*)(xr + k0 + 4);
        As[ak + 0][ar] = a0.x; As[ak + 1][ar] = a0.y;
        As[ak + 2][ar] = a0.z; As[ak + 3][ar] = a0.w;
        As[ak + 4][ar] = a1.x; As[ak + 5][ar] = a1.y;
        As[ak + 6][ar] = a1.z; As[ak + 7][ar] = a1.w;
        *(float4*)&Bs[bk][bc] =
            *(const float4*)(W + (size_t)(k0 + bk) * P + bn + bc);
        *(float4*)&Bs[bk + 8][bc] =
            *(const float4*)(W + (size_t)(k0 + bk + 8) * P + bn + bc);
        __syncthreads();
#pragma unroll
        for (int kk = 0; kk < GBK; kk++) {
            float4 av0 = *(const float4*)&As[kk][tr * 8];
            float4 av1 = *(const float4*)&As[kk][tr * 8 + 4];
            float4 bv0 = *(const float4*)&Bs[kk][tc * 8];
            float4 bv1 = *(const float4*)&Bs[kk][tc * 8 + 4];
            float a[8] = {av0.x, av0.y, av0.z, av0.w, av1.x, av1.y, av1.z, av1.w};
            float bb[8] = {bv0.x, bv0.y, bv0.z, bv0.w, bv1.x, bv1.y, bv1.z, bv1.w};
#pragma unroll
            for (int i = 0; i < 8; i++)
#pragma unroll
                for (int j = 0; j < 8; j++)
                    acc[i][j] = fmaf(a[i], bb[j], acc[i][j]);
        }
        __syncthreads();
    }

    float bb0[8];
#pragma unroll
    for (int j = 0; j < 8; j++) bb0[j] = bias[bn + tc * 8 + j];
#pragma unroll
    for (int i = 0; i < 8; i++) {
        size_t row = bm + tr * 8 + i;
        float4 o0 = make_float4(acc[i][0] + bb0[0], acc[i][1] + bb0[1],
                                acc[i][2] + bb0[2], acc[i][3] + bb0[3]);
        float4 o1 = make_float4(acc[i][4] + bb0[4], acc[i][5] + bb0[5],
                                acc[i][6] + bb0[6], acc[i][7] + bb0[7]);
        *(float4*)(C + row * P + bn + tc * 8)     = o0;
        *(float4*)(C + row * P + bn + tc * 8 + 4) = o1;
    }
}

// ---------------- small SGEMM (layer 3, P=12), bounds-checked ----------------
#define BM 64
#define BN 64
#define BKT 16
__global__ void gemm_kernel(const float* __restrict__ X, const float* __restrict__ W,
                            const float* __restrict__ bias, float* __restrict__ C,
                            int D, int P) {
    __shared__ float As[BKT][BM];
    __shared__ float Bs[BKT][BN];
    int bm = blockIdx.x * BM;
    int bn = blockIdx.y * BN;
    int tid = threadIdx.x;
    int tr = tid >> 4, tc = tid & 15;
    float acc[4][4] = {};

    for (int k0 = 0; k0 < D; k0 += BKT) {
        for (int t = tid; t < BM * BKT; t += 256) {
            int m = t >> 4, k = t & 15;
            As[k][m] = X[(size_t)(bm + m) * D + k0 + k];
        }
        for (int t = tid; t < BKT * BN; t += 256) {
            int k = t >> 6, n = t & 63;
            int nn = bn + n;
            Bs[k][n] = (nn < P) ? W[(size_t)(k0 + k) * P + nn] : 0.f;
        }
        __syncthreads();
#pragma unroll
        for (int kk = 0; kk < BKT; kk++) {
            float4 av = *(const float4*)&As[kk][tr * 4];
            float4 bv = *(const float4*)&Bs[kk][tc * 4];
            float a[4] = {av.x, av.y, av.z, av.w};
            float bb[4] = {bv.x, bv.y, bv.z, bv.w};
#pragma unroll
            for (int i = 0; i < 4; i++)
#pragma unroll
                for (int j = 0; j < 4; j++)
                    acc[i][j] = fmaf(a[i], bb[j], acc[i][j]);
        }
        __syncthreads();
    }
#pragma unroll
    for (int i = 0; i < 4; i++) {
        int row = bm + tr * 4 + i;
#pragma unroll
        for (int j = 0; j < 4; j++) {
            int col = bn + tc * 4 + j;
            if (col < P) C[(size_t)row * P + col] = acc[i][j] + bias[col];
        }
    }
}

// ---------------- attention, c=128 layers (block per node); packed QKVS ----------------
__global__ void attn128_kernel(const float* __restrict__ pk,
                               const float* __restrict__ resid,
                               float* __restrict__ outp, int do_tanh) {
    __shared__ float sq[128];
    __shared__ float al[16];
    __shared__ int   nb[16];
    int i = blockIdx.x;
    int t = threadIdx.x;
    if (t < 16) nb[t] = g_nbr[i * 16 + t];
    sq[t] = pk[(size_t)i * 512 + t];            // Q at offset 0
    __syncthreads();

    int w = t >> 5, l = t & 31;
#pragma unroll
    for (int ee = 0; ee < 4; ee++) {
        int e = (w << 2) + ee;
        int j = nb[e];
        const float* kj = pk + (size_t)j * 512 + 128;   // K at offset 128
        float a = sq[l] * kj[l];
        a = fmaf(sq[l + 32], kj[l + 32], a);
        a = fmaf(sq[l + 64], kj[l + 64], a);
        a = fmaf(sq[l + 96], kj[l + 96], a);
#pragma unroll
        for (int o = 16; o > 0; o >>= 1) a += __shfl_xor_sync(0xffffffffu, a, o);
        if (l == 0) al[e] = a * 0.08838834764831845f;   // 1/sqrt(128)
    }
    __syncthreads();
    if (t < 32) {
        float a = (l < 16) ? al[l] : -__int_as_float(0x7f800000);
        float m = a;
#pragma unroll
        for (int o = 16; o > 0; o >>= 1) m = fmaxf(m, __shfl_xor_sync(0xffffffffu, m, o));
        float ex = (l < 16) ? expf(a - m) : 0.f;
        float sm = ex;
#pragma unroll
        for (int o = 16; o > 0; o >>= 1) sm += __shfl_xor_sync(0xffffffffu, sm, o);
        if (l < 16) al[l] = ex / sm;
    }
    __syncthreads();

    float acc = pk[(size_t)i * 512 + 384 + t];          // S at offset 384
#pragma unroll
    for (int e = 0; e < 16; e++)
        acc = fmaf(al[e], pk[(size_t)nb[e] * 512 + 256 + t], acc);  // V at 256
    if (resid) acc += resid[(size_t)i * 128 + t];
    outp[(size_t)i * 128 + t] = do_tanh ? tanhf(acc) : acc;
}

// ---------------- attention, c=3 final layer (warp per node); packed P=12 ----------------
__global__ void attn3_kernel(const float* __restrict__ pk, float* __restrict__ outp) {
    int gt = blockIdx.x * blockDim.x + threadIdx.x;
    int i = gt >> 5;
    int l = gt & 31;
    if (i >= NPTS) return;
    int j = 0;
    float a = -__int_as_float(0x7f800000);
    if (l < 16) {
        j = g_nbr[i * 16 + l];
        float qx = pk[i * 12 + 0], qy = pk[i * 12 + 1], qz = pk[i * 12 + 2];
        a = fmaf(qx, pk[j * 12 + 3], fmaf(qy, pk[j * 12 + 4], qz * pk[j * 12 + 5]))
            * 0.5773502691896258f;   // 1/sqrt(3)
    }
    float m = a;
#pragma unroll
    for (int o = 16; o > 0; o >>= 1) m = fmaxf(m, __shfl_xor_sync(0xffffffffu, m, o));
    float ex = (l < 16) ? expf(a - m) : 0.f;
    float sm = ex;
#pragma unroll
    for (int o = 16; o > 0; o >>= 1) sm += __shfl_xor_sync(0xffffffffu, sm, o);
    float wgt = ex / sm;
    float vx = 0.f, vy = 0.f, vz = 0.f;
    if (l < 16) {
        vx = wgt * pk[j * 12 + 6];
        vy = wgt * pk[j * 12 + 7];
        vz = wgt * pk[j * 12 + 8];
    }
#pragma unroll
    for (int o = 16; o > 0; o >>= 1) {
        vx += __shfl_xor_sync(0xffffffffu, vx, o);
        vy += __shfl_xor_sync(0xffffffffu, vy, o);
        vz += __shfl_xor_sync(0xffffffffu, vz, o);
    }
    if (l == 0) {
        outp[i * 3 + 0] = vx + pk[i * 12 + 9];
        outp[i * 3 + 1] = vy + pk[i * 12 + 10];
        outp[i * 3 + 2] = vz + pk[i * 12 + 11];
    }
}

// ---------------- host ----------------
extern "C" void kernel_launch(void* const* d_in, const int* in_sizes, int n_in,
                              void* d_out, int out_size) {
    const float* x = (const float*)d_in[1];
    const float* W1[4] = {(const float*)d_in[2], (const float*)d_in[4],
                          (const float*)d_in[6], (const float*)d_in[8]};
    const float* B1[4] = {(const float*)d_in[3], (const float*)d_in[5],
                          (const float*)d_in[7], (const float*)d_in[9]};
    const float* W2[4] = {(const float*)d_in[10], (const float*)d_in[12],
                          (const float*)d_in[14], (const float*)d_in[16]};
    const float* B2[4] = {(const float*)d_in[11], (const float*)d_in[13],
                          (const float*)d_in[15], (const float*)d_in[17]};
    const float* W3[4] = {(const float*)d_in[18], (const float*)d_in[20],
                          (const float*)d_in[22], (const float*)d_in[24]};
    const float* B3[4] = {(const float*)d_in[19], (const float*)d_in[21],
                          (const float*)d_in[23], (const float*)d_in[25]};
    float* out = (float*)d_out;

    float *qkvs, *h1, *h2, *Wp1, *Wp2, *Wp3, *Bp1, *Bp2, *Bp3;
    cudaGetSymbolAddress((void**)&qkvs, g_qkvs);
    cudaGetSymbolAddress((void**)&h1,  g_h1);
    cudaGetSymbolAddress((void**)&h2,  g_h2);
    cudaGetSymbolAddress((void**)&Wp1, g_Wp1);
    cudaGetSymbolAddress((void**)&Wp2, g_Wp2);
    cudaGetSymbolAddress((void**)&Wp3, g_Wp3);
    cudaGetSymbolAddress((void**)&Bp1, g_Bp1);
    cudaGetSymbolAddress((void**)&Bp2, g_Bp2);
    cudaGetSymbolAddress((void**)&Bp3, g_Bp3);

    // Launch order chosen so the 4th launch (ncu capture slot) = knn_partial.
    prep_kernel<<<NPTS / 256, 256>>>(x);                                   // 1
    pack_b_kernel<<<1, 128>>>(B1[0], B1[1], B1[2], B1[3], Bp1, 128);       // 2
    pack_b_kernel<<<1, 128>>>(B2[0], B2[1], B2[2], B2[3], Bp2, 128);       // 3
    knn_partial_kernel<<<SPLITS * (NPTS / 128), 128>>>();                  // 4 <- profiled
    knn_merge_kernel<<<NPTS / 256, 256>>>();                               // 5
    pack_b_kernel<<<1, 128>>>(B3[0], B3[1], B3[2], B3[3], Bp3, 3);
    pack_w_kernel<<<(64 * 128 + 255) / 256, 256>>>(W1[0], W1[1], W1[2], W1[3], Wp1, 64, 128);
    pack_w_kernel<<<(128 * 128 + 255) / 256, 256>>>(W2[0], W2[1], W2[2], W2[3], Wp2, 128, 128);
    pack_w_kernel<<<(128 * 3 + 255) / 256, 256>>>(W3[0], W3[1], W3[2], W3[3], Wp3, 128, 3);

    // layer 1
    {
        dim3 grid(NPTS / GBM, 512 / GBN);
        gemm128_kernel<<<grid, 256>>>(x, Wp1, Bp1, qkvs, 64, 512);
    }
    attn128_kernel<<<NPTS, 128>>>(qkvs, nullptr, h1, 1);

    // layer 2
    {
        dim3 grid(NPTS / GBM, 512 / GBN);
        gemm128_kernel<<<grid, 256>>>(h1, Wp2, Bp2, qkvs, 128, 512);
    }
    attn128_kernel<<<NPTS, 128>>>(qkvs, h1, h2, 1);

    // layer 3
    {
        dim3 grid(NPTS / BM, 1);
        gemm_kernel<<<grid, 256>>>(h2, Wp3, Bp3, qkvs, 128, 12);
    }
    attn3_kernel<<<(NPTS * 32) / 128, 128>>>(qkvs, out);
}